// round 13
// baseline (speedup 1.0000x reference)
#include <cuda_runtime.h>
#include <cuda_bf16.h>
#include <mma.h>
#include <cstdint>

using namespace nvcuda;

// Problem constants (fixed by the dataset)
#define T_LOCAL   2048
#define S_GLOBAL  4096
#define NQ        16
#define NK        8
#define HN        128
#define WINDOW    1024

#define BM 64
#define BN 64
#define NTHREADS 256

// smem strides (floats); multiples of 4 (16B-aligned rows), not multiples of 32
#define LDQ 132
#define LDK 132
#define LDV 132
#define LDP 68

#define KH_FLOATS (64*LDK)
#define VT_FLOATS (64*LDV)
#define PH_FLOATS (64*LDP)

#define QH_OFF 0
#define KH_OFF (QH_OFF + 64*LDQ)
#define VT_OFF (KH_OFF + KH_FLOATS)            // 2 buffers (buffer 1 doubles as Ql staging)
#define PH_OFF (VT_OFF + 2*VT_FLOATS)          // 2 buffers
#define LR_OFF (PH_OFF + 2*PH_FLOATS)
#define SMEM_FLOATS (LR_OFF + 64)
#define SMEM_BYTES  (SMEM_FLOATS * 4)          // ~169 KB < 227 KB carveout

__device__ __forceinline__ float tf32_hi(float x) {
    float r;
    asm("cvt.rna.tf32.f32 %0, %1;" : "=f"(r) : "f"(x));
    return r;
}

__global__ __launch_bounds__(NTHREADS, 1)
void sdpa_zigzag_kernel(const float* __restrict__ q,
                        const float* __restrict__ k,
                        const float* __restrict__ v,
                        float* __restrict__ out)
{
    // LPT: heavy tiles (full sliding window) scheduled first
    const int tileIdx = 31 - blockIdx.x;
    const int h       = blockIdx.y;
    const int hk      = h >> 1;               // GQA kv head

    const int t0   = tileIdx * BM;
    const int row0 = (t0 < 1024) ? t0 : t0 + 2048;   // zigzag global row

    const int tid = threadIdx.x;
    const int wid = tid >> 5;

    extern __shared__ float smem[];
    float* Qh  = smem + QH_OFF;
    float* Kh  = smem + KH_OFF;
    float* VtB = smem + VT_OFF;   // 2 buffers
    float* PhB = smem + PH_OFF;   // 2 buffers
    float* Lr  = smem + LR_OFF;
    float* QlT = VtB + VT_FLOATS; // Ql staging = Vt buffer 1 (dead until V-STS(it=0))

    const float SCALE = 0.08838834764831845f;  // 1/sqrt(128)

    // Q/K STS assignment: row = tid&63, 32-wide d-chunk
    const int lc  = tid & 63;
    const int ldc = (tid >> 6) * 32;

    // ---- load Q tile, pre-scaled, split hi/lo (2xTF32 on the Q side) ----
    {
        const float* qp = q + ((size_t)(t0 + lc) * NQ + h) * HN + ldc;
        #pragma unroll
        for (int k4 = 0; k4 < 8; k4++) {
            float4 val = *(const float4*)(qp + k4 * 4);
            int d = ldc + k4 * 4;
            float xs[4] = {val.x * SCALE, val.y * SCALE, val.z * SCALE, val.w * SCALE};
            #pragma unroll
            for (int e = 0; e < 4; e++) {
                float hi = tf32_hi(xs[e]);
                Qh[lc * LDQ + d + e]  = hi;
                QlT[lc * LDV + d + e] = xs[e] - hi;   // exact in fp32
            }
        }
    }

    // softmax/epilogue mapping: row r = tid>>2, d-group dg = tid&3
    const int r    = tid >> 2;
    const int dg   = tid & 3;
    const int rowG = row0 + r;
    const int loG  = rowG - (WINDOW - 1);
    float Lacc = 0.f;

    // wmma warp tiling
    const int mt  = wid >> 1;            // m-tile 0..3 (16 rows each)
    const int nh  = wid & 1;
    const int nbS = nh * 2;              // QK: n-tiles nbS, nbS+1
    const int nbO = nh * 4;              // PV: n-tiles nbO..nbO+3

    wmma::fragment<wmma::accumulator, 16, 16, 8, float> Oacc[4];
    #pragma unroll
    for (int t = 0; t < 4; t++) wmma::fill_fragment(Oacc[t], 0.f);

    // key-block range
    int gLo = row0 - (WINDOW - 1); if (gLo < 0) gLo = 0;
    const int blk0   = (gLo / BN) * BN;
    const int blkEnd = row0 + BM - 1;
    const int nblk   = (blkEnd - blk0) / BN + 1;

    float4 kreg[8];

    // ---- prologue: LDG + STS tile 0 (K -> Kh, V -> Vt buffer 0) ----
    {
        const int blk = blk0;
        const int off = (blk < 1024) ? 0 : ((blk < 3072) ? 1024 : -2048);
        const float* kp = k + ((size_t)(blk + lc + off) * NK + hk) * HN + ldc;
        #pragma unroll
        for (int k4 = 0; k4 < 8; k4++)
            kreg[k4] = *(const float4*)(kp + k4 * 4);
        #pragma unroll
        for (int k4 = 0; k4 < 8; k4++) {
            int d = ldc + k4 * 4;
            Kh[lc * LDK + d + 0] = tf32_hi(kreg[k4].x);
            Kh[lc * LDK + d + 1] = tf32_hi(kreg[k4].y);
            Kh[lc * LDK + d + 2] = tf32_hi(kreg[k4].z);
            Kh[lc * LDK + d + 3] = tf32_hi(kreg[k4].w);
        }
        float4 vreg0[8];
        #pragma unroll
        for (int e = 0; e < 8; e++) {
            int lin = tid + e * NTHREADS;
            int c2  = lin >> 5;
            int d4  = lin & 31;
            vreg0[e] = *(const float4*)(v + ((size_t)(blk + c2 + off) * NK + hk) * HN + d4 * 4);
        }
        #pragma unroll
        for (int e = 0; e < 8; e++) {
            int lin = tid + e * NTHREADS;
            int c2  = lin >> 5;
            int d4  = lin & 31;
            float4 t4;
            t4.x = tf32_hi(vreg0[e].x); t4.y = tf32_hi(vreg0[e].y);
            t4.z = tf32_hi(vreg0[e].z); t4.w = tf32_hi(vreg0[e].w);
            *(float4*)(VtB + c2 * LDV + d4 * 4) = t4;
        }
    }
    __syncthreads();   // Q (hi + staged lo) + tile 0 visible

    // ---- register-cache loop-invariant Q A-fragments (hi + lo; 128 regs).
    //      QlT consumed HERE, before any thread's sync B(0): the barrier at
    //      sync B(0) separates these reads from the V-STS into buffer 1. ----
    wmma::fragment<wmma::matrix_a, 16, 16, 8, wmma::precision::tf32, wmma::row_major> aQh[16], aQl[16];
    #pragma unroll
    for (int kk = 0; kk < 16; kk++) {
        wmma::load_matrix_sync(aQh[kk], Qh  + (mt * 16) * LDQ + kk * 8, LDQ);
        wmma::load_matrix_sync(aQl[kk], QlT + (mt * 16) * LDV + kk * 8, LDV);
    }

    // ---- tile body; Vt/Ph/Vtn become compile-time smem offsets at both
    //      call sites after inlining (no runtime (it&1) pointer math) ----
    auto tile_body = [&](int it, float* __restrict__ Vt, float* __restrict__ Ph,
                         float* __restrict__ Vtn) {
        const int blk = blk0 + it * BN;
        const bool hasNext = (it + 1 < nblk);
        const int nb2  = blk + BN;
        const int offN = (nb2 < 1024) ? 0 : ((nb2 < 3072) ? 1024 : -2048);
        const bool interior = (blk <= row0 - 64) && (blk >= row0 - 960);

        // prefetch next K (32 staging regs live across QK; V loaded later)
        if (hasNext) {
            const float* kp = k + ((size_t)(nb2 + lc + offN) * NK + hk) * HN + ldc;
            #pragma unroll
            for (int k4 = 0; k4 < 8; k4++)
                kreg[k4] = *(const float4*)(kp + k4 * 4);
        }

        // S = Q K^T via 2xTF32 wmma: (aQh + aQl) x Kh; S -> Ph
        {
            wmma::fragment<wmma::accumulator, 16, 16, 8, float> acc[2];
            wmma::fill_fragment(acc[0], 0.f);
            wmma::fill_fragment(acc[1], 0.f);

            #pragma unroll
            for (int kk = 0; kk < 16; kk++) {
                const int k0 = kk * 8;
                #pragma unroll
                for (int t = 0; t < 2; t++) {
                    const int n0 = (nbS + t) * 16;
                    wmma::fragment<wmma::matrix_b, 16, 16, 8, wmma::precision::tf32, wmma::col_major> b_hi;
                    wmma::load_matrix_sync(b_hi, Kh + n0 * LDK + k0, LDK);
                    wmma::mma_sync(acc[t], aQh[kk], b_hi, acc[t]);
                    wmma::mma_sync(acc[t], aQl[kk], b_hi, acc[t]);
                }
            }
            wmma::store_matrix_sync(Ph + (mt * 16) * LDP + (nbS + 0) * 16, acc[0], LDP, wmma::mem_row_major);
            wmma::store_matrix_sync(Ph + (mt * 16) * LDP + (nbS + 1) * 16, acc[1], LDP, wmma::mem_row_major);
        }
        __syncthreads();   // sync B: S visible; Kh reads complete; PV(it-1) complete

        // phase: K STS (kills kreg) -> V LDG -> masked exp -> V STS.
        // kreg and vreg never co-live; V latency covered by the exp block.
        {
            if (hasNext) {
                #pragma unroll
                for (int k4 = 0; k4 < 8; k4++) {
                    int d = ldc + k4 * 4;
                    Kh[lc * LDK + d + 0] = tf32_hi(kreg[k4].x);
                    Kh[lc * LDK + d + 1] = tf32_hi(kreg[k4].y);
                    Kh[lc * LDK + d + 2] = tf32_hi(kreg[k4].z);
                    Kh[lc * LDK + d + 3] = tf32_hi(kreg[k4].w);
                }
            }

            float4 vreg[8];
            if (hasNext) {
                #pragma unroll
                for (int e = 0; e < 8; e++) {
                    int lin = tid + e * NTHREADS;
                    int c2  = lin >> 5;
                    int d4  = lin & 31;
                    vreg[e] = *(const float4*)(v + ((size_t)(nb2 + c2 + offN) * NK + hk) * HN + d4 * 4);
                }
            }

            const int cbase = dg * 16;
            float lsum = 0.f;
            if (interior) {
                #pragma unroll
                for (int j = 0; j < 4; j++) {
                    float4 sv = *(float4*)(Ph + r * LDP + cbase + j * 4);
                    float pr[4];
                    pr[0] = tf32_hi(__expf(sv.x));
                    pr[1] = tf32_hi(__expf(sv.y));
                    pr[2] = tf32_hi(__expf(sv.z));
                    pr[3] = tf32_hi(__expf(sv.w));
                    lsum += (pr[0] + pr[1]) + (pr[2] + pr[3]);
                    *(float4*)(Ph + r * LDP + cbase + j * 4) = make_float4(pr[0], pr[1], pr[2], pr[3]);
                }
            } else {
                #pragma unroll
                for (int j = 0; j < 4; j++) {
                    float4 sv = *(float4*)(Ph + r * LDP + cbase + j * 4);
                    float se[4] = {sv.x, sv.y, sv.z, sv.w};
                    float pr[4];
                    #pragma unroll
                    for (int e = 0; e < 4; e++) {
                        int g = blk + cbase + j * 4 + e;
                        // window [loG, rowG], width exactly 1024: single compare
                        bool ok = (unsigned)(g - loG) < (unsigned)WINDOW;
                        float pv = ok ? tf32_hi(__expf(se[e])) : 0.f;
                        pr[e] = pv;
                        lsum += pv;
                    }
                    *(float4*)(Ph + r * LDP + cbase + j * 4) = make_float4(pr[0], pr[1], pr[2], pr[3]);
                }
            }
            lsum += __shfl_xor_sync(0xffffffffu, lsum, 1);
            lsum += __shfl_xor_sync(0xffffffffu, lsum, 2);
            Lacc += lsum;

            if (hasNext) {
                // V -> other buffer: last reader PV(it-1) precedes sync B(it);
                // consumer PV(it+1) behind sync C(it)+B(it+1); it=0 staging of
                // Ql in buffer 1 was consumed before sync B(0).
                #pragma unroll
                for (int e = 0; e < 8; e++) {
                    int lin = tid + e * NTHREADS;
                    int c2  = lin >> 5;
                    int d4  = lin & 31;
                    float4 t4;
                    t4.x = tf32_hi(vreg[e].x); t4.y = tf32_hi(vreg[e].y);
                    t4.z = tf32_hi(vreg[e].z); t4.w = tf32_hi(vreg[e].w);
                    *(float4*)(Vtn + c2 * LDV + d4 * 4) = t4;
                }
            }
        }
        __syncthreads();   // sync C: P + next K/V visible

        // O += P V on tensor pipe (single-term: P and V pre-rounded)
        {
            #pragma unroll
            for (int kk = 0; kk < 8; kk++) {
                const int k0 = kk * 8;
                wmma::fragment<wmma::matrix_a, 16, 16, 8, wmma::precision::tf32, wmma::row_major> a;
                wmma::load_matrix_sync(a, Ph + (mt * 16) * LDP + k0, LDP);
                #pragma unroll
                for (int t = 0; t < 4; t++) {
                    const int n0 = (nbO + t) * 16;
                    wmma::fragment<wmma::matrix_b, 16, 16, 8, wmma::precision::tf32, wmma::row_major> b;
                    wmma::load_matrix_sync(b, Vt + k0 * LDV + n0, LDV);
                    wmma::mma_sync(Oacc[t], a, b, Oacc[t]);
                }
            }
        }
        // No trailing barrier (protected by next iteration's sync B/C).
    };

    // 2x-unrolled drive loop: buffer pointers are constants at each call site.
    // nblk is block-uniform, so the guarded second call (and its barriers)
    // is executed by all threads or none.
    for (int it = 0; it < nblk; it += 2) {
        tile_body(it,     VtB,             PhB,             VtB + VT_FLOATS);
        if (it + 1 < nblk)
            tile_body(it + 1, VtB + VT_FLOATS, PhB + PH_FLOATS, VtB);
    }

    // ---- epilogue: dump O fragments to smem (reuse Qh area), normalize, store ----
    if (dg == 0) Lr[r] = Lacc;     // Lr region untouched by loop; no race
    __syncthreads();               // all PV reads done before Qh reuse; Lr visible
    #pragma unroll
    for (int t = 0; t < 4; t++)
        wmma::store_matrix_sync(Qh + (mt * 16) * LDQ + (nbO + t) * 16, Oacc[t], LDQ, wmma::mem_row_major);
    __syncthreads();

    {
        const float inv = 1.0f / Lr[r];
        const int tq = t0 + r;
        const float* src = Qh + r * LDQ;
        float* op = out + (size_t)tq * (NQ * HN) + h * HN + dg * 4;
        #pragma unroll
        for (int j = 0; j < 8; j++) {
            float4 val = *(const float4*)(src + dg * 4 + j * 16);
            val.x *= inv; val.y *= inv; val.z *= inv; val.w *= inv;
            *(float4*)(op + j * 16) = val;
        }
    }
}

extern "C" void kernel_launch(void* const* d_in, const int* in_sizes, int n_in,
                              void* d_out, int out_size) {
    const float* q = (const float*)d_in[0];   // [2048, 16, 128]
    const float* k = (const float*)d_in[1];   // [4096, 8, 128]
    const float* v = (const float*)d_in[2];   // [4096, 8, 128]
    // d_in[3] = cu_seqlens (unused; single sub-sequence)
    float* out = (float*)d_out;               // [2048, 2048]

    cudaFuncSetAttribute(sdpa_zigzag_kernel,
                         cudaFuncAttributeMaxDynamicSharedMemorySize, SMEM_BYTES);

    dim3 grid(T_LOCAL / BM, NQ);              // (32, 16)
    sdpa_zigzag_kernel<<<grid, NTHREADS, SMEM_BYTES>>>(q, k, v, out);
}